// round 8
// baseline (speedup 1.0000x reference)
#include <cuda_runtime.h>
#include <math.h>
#include <string.h>

// ============================================================================
// MNIST_CNN2D_TWN forward pass, f32, fully fused pipeline.
//
// R7 change: packed fp32x2 FMA (PTX fma.rn.f32x2 -> SASS FFMA2) in the three
// FMA-bound kernels (conv1/conv2/fc1), with operand layouts arranged so every
// packed operand comes straight from memory (no per-FMA packing MOVs):
//   conv2: acc pairs across oc; weight pairs free from LDS.128, inputs stored
//          duplicated (v,v) in dynamic SMEM (62.5KB -> FuncSetAttribute).
//   conv1: acc pairs across dx; inputs stored as consecutive pairs
//          (img[i],img[i+1]); weights duplicated into registers once.
//   fc1:   acc pairs across m; A pairs free from LDS.128, B duplicated in
//          SMEM with q-major permutation (bank-conflict-free LDS.64).
// Math stays exact fp32 (FFMA2 = 2x IEEE fp32 FMA), so rel_err unchanged.
//
// Pipeline (unchanged): quantize ternary weights; conv1+bias+stats+maxpool;
// bn1 affine; conv2 (+lazy bn1/relu on load) +bias+stats+maxpool; bn2;
// fc1 SGEMM (+lazy bn2/relu) +bias+stats; bn3; fc2 (+lazy bn3/relu).
// Legality of pool/bn swap: g=1>0 so bn is increasing affine; relu monotone.
// Stats are taken over full pre-pool conv outputs, matching reference.
// ============================================================================

#define NIMG 4096
typedef unsigned long long ull;

// ---------------- f32x2 helpers ----------------
__device__ __forceinline__ ull pack2(float lo, float hi) {
    float2 t = make_float2(lo, hi);
    ull r; memcpy(&r, &t, 8); return r;
}
__device__ __forceinline__ float2 unpack2(ull v) {
    float2 t; memcpy(&t, &v, 8); return t;
}
__device__ __forceinline__ ull ffma2(ull a, ull b, ull c) {
    ull d;
    asm("fma.rn.f32x2 %0, %1, %2, %3;" : "=l"(d) : "l"(a), "l"(b), "l"(c));
    return d;
}

// ---------------- device scratch (static; no allocation) ----------------
__device__ float g_q1[800];                      // [32][25] ternary
__device__ float g_q2t[51200];                   // [(ic*25+kk)][64] ternary (transposed)
__device__ float g_qf1[524288];                  // [512][1024] ternary
__device__ float g_qf2[5120];                    // [10][512] ternary
__device__ float g_pool1[(size_t)NIMG * 32 * 144]; // raw pooled conv1 (pre-bn)
__device__ float g_pool2[(size_t)NIMG * 64 * 16];  // raw pooled conv2 (pre-bn)
__device__ float g_z[(size_t)NIMG * 512];          // fc1 pre-bn output
__device__ float g_sum1[32], g_sq1[32], g_a1[32], g_d1[32];
__device__ float g_sum2[64], g_sq2[64], g_a2[64], g_d2[64];
__device__ float g_sum3[512], g_sq3[512], g_a3[512], g_d3[512];
__device__ unsigned g_tmax[4];                   // maxabs bit patterns (w1,w2,wf1,wf2)

// ---------------- stats zeroing ----------------
__global__ void zero_stats_kernel() {
    int i = threadIdx.x;
    if (i < 32) { g_sum1[i] = 0.f; g_sq1[i] = 0.f; }
    if (i < 64) { g_sum2[i] = 0.f; g_sq2[i] = 0.f; }
    if (i < 4)  { g_tmax[i] = 0u; }
    for (int j = i; j < 512; j += blockDim.x) { g_sum3[j] = 0.f; g_sq3[j] = 0.f; }
}

// ---------------- grid-wide maxabs reduction ----------------
// Non-negative floats compare identically as unsigned ints; max is
// order-independent, so atomicMax is deterministic.
__global__ void maxabs_kernel(const float* __restrict__ w, int n, int which) {
    __shared__ float red[8];
    int tid = threadIdx.x;
    float m = 0.f;
    for (int i = blockIdx.x * blockDim.x + tid; i < n; i += gridDim.x * blockDim.x)
        m = fmaxf(m, fabsf(w[i]));
    #pragma unroll
    for (int o = 16; o; o >>= 1) m = fmaxf(m, __shfl_xor_sync(0xffffffffu, m, o));
    if ((tid & 31) == 0) red[tid >> 5] = m;
    __syncthreads();
    if (tid < 32) {
        float v = (tid < (int)(blockDim.x >> 5)) ? red[tid] : 0.f;
        #pragma unroll
        for (int o = 4; o; o >>= 1) v = fmaxf(v, __shfl_xor_sync(0xffffffffu, v, o));
        if (tid == 0) atomicMax(&g_tmax[which], __float_as_uint(v));
    }
}

// which: 0 -> g_q1 (n=800), 2 -> g_qf1, 3 -> g_qf2
__global__ void quantize_kernel(const float* __restrict__ w, int n, int which) {
    float t = 0.05f * __uint_as_float(g_tmax[which]);
    float* q = (which == 0) ? g_q1 : (which == 2) ? g_qf1 : g_qf2;
    int i = blockIdx.x * blockDim.x + threadIdx.x;
    if (i < n) {
        float v = w[i];
        q[i] = (v > t ? 1.f : 0.f) - (v < -t ? 1.f : 0.f);
    }
}

// w2 [oc=64][ic=32][5][5] -> g_q2t[(ic*25+kk)*64 + oc]
__global__ void quantize_w2_kernel(const float* __restrict__ w) {
    float t = 0.05f * __uint_as_float(g_tmax[1]);
    int i = blockIdx.x * blockDim.x + threadIdx.x;
    if (i < 51200) {
        float v = w[i];
        float q = (v > t ? 1.f : 0.f) - (v < -t ? 1.f : 0.f);
        int oc = i / 800;
        int rem = i - oc * 800;
        g_q2t[rem * 64 + oc] = q;
    }
}

// ---------------- bn affine finalize: a = g/sqrt(var+eps), d = be - mean*a ----
__global__ void finalize_kernel(const float* __restrict__ gam,
                                const float* __restrict__ bet, int which) {
    const float* sum; const float* sq; float* a; float* d; int C; float inv;
    if (which == 0)      { sum = g_sum1; sq = g_sq1; a = g_a1; d = g_d1; C = 32;  inv = 1.f / 2359296.f; }
    else if (which == 1) { sum = g_sum2; sq = g_sq2; a = g_a2; d = g_d2; C = 64;  inv = 1.f / 262144.f;  }
    else                 { sum = g_sum3; sq = g_sq3; a = g_a3; d = g_d3; C = 512; inv = 1.f / 4096.f;    }
    int i = blockIdx.x * blockDim.x + threadIdx.x;
    if (i < C) {
        float m = sum[i] * inv;
        float v = sq[i] * inv - m * m;
        float ai = gam[i] / sqrtf(v + 1e-5f);
        a[i] = ai;
        d[i] = bet[i] - m * ai;
    }
}

// ---------------- conv1: 1->32, 5x5, + bias + stats + maxpool2 ----------------
// f32x2: acc pairs over (dx0,dx1). Input consecutive-pairs array imgd
// (origin ox always even -> aligned ulonglong2 loads). Weights dup'd in regs.
__global__ __launch_bounds__(256) void conv1_kernel(const float* __restrict__ x,
                                                    const float* __restrict__ b1) {
    __shared__ float img[784];
    __shared__ __align__(16) ull imgd[784];     // imgd[i] = (img[i], img[i+1])
    __shared__ float wsh[800];
    __shared__ float ssum[32], ssq[32];
    int n = blockIdx.x, tid = threadIdx.x;

    for (int i = tid; i < 784; i += 256) img[i] = x[(size_t)n * 784 + i];
    for (int i = tid; i < 800; i += 256) wsh[i] = g_q1[i];
    if (tid < 32) { ssum[tid] = 0.f; ssq[tid] = 0.f; }
    __syncthreads();
    for (int i = tid; i < 784; i += 256)
        imgd[i] = pack2(img[i], (i < 783) ? img[i + 1] : 0.f);
    __syncthreads();

    int c = tid >> 3, sub = tid & 7;
    ull wrd[25];
    #pragma unroll
    for (int k = 0; k < 25; k++) { float w = wsh[c * 25 + k]; wrd[k] = pack2(w, w); }
    float bias = b1[c];
    float lsum = 0.f, lsq = 0.f;
    float* outp = g_pool1 + ((size_t)n * 32 + c) * 144;

    for (int k2 = 0; k2 < 18; k2++) {           // 144 pooled cells / 8 subs
        int p = sub * 18 + k2;
        int py = p / 12, px = p - py * 12;
        int oy = 2 * py, ox = 2 * px;           // ox even -> aligned pairs
        ull a0 = 0ull, a1 = 0ull;               // (dx0,dx1) accs for dy=0 / dy=1
        #pragma unroll
        for (int r = 0; r < 6; r++) {
            int rb = (oy + r) * 28 + ox;        // even index
            ulonglong2 t01 = *reinterpret_cast<const ulonglong2*>(&imgd[rb]);
            ulonglong2 t23 = *reinterpret_cast<const ulonglong2*>(&imgd[rb + 2]);
            ull t4 = imgd[rb + 4];
            ull rp[5] = { t01.x, t01.y, t23.x, t23.y, t4 };
            if (r < 5) {                         // dy=0, ky=r
                #pragma unroll
                for (int kx = 0; kx < 5; kx++) a0 = ffma2(rp[kx], wrd[r * 5 + kx], a0);
            }
            if (r > 0) {                         // dy=1, ky=r-1
                #pragma unroll
                for (int kx = 0; kx < 5; kx++) a1 = ffma2(rp[kx], wrd[(r - 1) * 5 + kx], a1);
            }
        }
        float2 u0 = unpack2(a0), u1 = unpack2(a1);
        float v00 = u0.x + bias, v01 = u0.y + bias;
        float v10 = u1.x + bias, v11 = u1.y + bias;
        lsum += v00 + v01 + v10 + v11;
        lsq = fmaf(v00, v00, lsq); lsq = fmaf(v01, v01, lsq);
        lsq = fmaf(v10, v10, lsq); lsq = fmaf(v11, v11, lsq);
        float mx = fmaxf(fmaxf(v00, v01), fmaxf(v10, v11));
        outp[p] = mx;
    }
    atomicAdd(&ssum[c], lsum);
    atomicAdd(&ssq[c], lsq);
    __syncthreads();
    if (tid < 32) { atomicAdd(&g_sum1[tid], ssum[tid]); atomicAdd(&g_sq1[tid], ssq[tid]); }
}

// ---------------- conv2: 32->64, 5x5, + bias + stats + maxpool2 ----------------
// f32x2: acc pairs over oc. Weight pairs free from LDS.128 of [..][oc] tile;
// inputs stored duplicated (v,v) in dynamic SMEM.
// dynamic smem: ishd[4608] ull (36864B) + wt[6400] float (25600B) = 62464B
#define CONV2_DSMEM (4608 * 8 + 6400 * 4)
__global__ __launch_bounds__(256) void conv2_kernel(const float* __restrict__ b2) {
    extern __shared__ __align__(16) ull dynsm[];
    ull* ishd = dynsm;                           // 4608 duplicated inputs
    float* wt = (float*)(dynsm + 4608);          // 6400 weight tile
    __shared__ float ssum[64], ssq[64];
    int n = blockIdx.x, tid = threadIdx.x;

    for (int i = tid; i < 4608; i += 256) {
        int c = i / 144;
        float raw = g_pool1[(size_t)n * 4608 + i];
        float v = fmaxf(fmaf(g_a1[c], raw, g_d1[c]), 0.f);
        reinterpret_cast<float2*>(ishd)[i] = make_float2(v, v);
    }
    if (tid < 64) { ssum[tid] = 0.f; ssq[tid] = 0.f; }

    int oc4 = tid >> 4;                  // 0..15, ocs = oc4*4 .. +3
    int pg = tid & 15, ty = pg >> 2, tx = pg & 3;
    int y0 = 2 * ty, x0 = 2 * tx;        // raw output 2x2 tile origin (8x8 grid)

    ull acc[2][2][2];                    // [oc-pair][dy][dx], each = (oc_lo,oc_hi)
    #pragma unroll
    for (int p = 0; p < 2; p++)
        #pragma unroll
        for (int dy = 0; dy < 2; dy++)
            #pragma unroll
            for (int dx = 0; dx < 2; dx++) acc[p][dy][dx] = 0ull;

    for (int icb = 0; icb < 8; icb++) {          // ic tiles of 4
        __syncthreads();
        for (int i = tid; i < 6400; i += 256) wt[i] = g_q2t[icb * 6400 + i];
        __syncthreads();
        for (int icl = 0; icl < 4; icl++) {
            int base = (icb * 4 + icl) * 144;
            #pragma unroll
            for (int ky = 0; ky < 5; ky++) {
                int rb = base + (y0 + ky) * 12 + x0;
                ull r0d[6], r1d[6];
                #pragma unroll
                for (int j = 0; j < 6; j++) { r0d[j] = ishd[rb + j]; r1d[j] = ishd[rb + 12 + j]; }
                #pragma unroll
                for (int kx = 0; kx < 5; kx++) {
                    ulonglong2 wp = *reinterpret_cast<const ulonglong2*>(
                        &wt[(((icl * 5 + ky) * 5 + kx) << 6) + (oc4 << 2)]);
                    ull i00 = r0d[kx], i01 = r0d[kx + 1];
                    ull i10 = r1d[kx], i11 = r1d[kx + 1];
                    acc[0][0][0] = ffma2(wp.x, i00, acc[0][0][0]);
                    acc[0][0][1] = ffma2(wp.x, i01, acc[0][0][1]);
                    acc[0][1][0] = ffma2(wp.x, i10, acc[0][1][0]);
                    acc[0][1][1] = ffma2(wp.x, i11, acc[0][1][1]);
                    acc[1][0][0] = ffma2(wp.y, i00, acc[1][0][0]);
                    acc[1][0][1] = ffma2(wp.y, i01, acc[1][0][1]);
                    acc[1][1][0] = ffma2(wp.y, i10, acc[1][1][0]);
                    acc[1][1][1] = ffma2(wp.y, i11, acc[1][1][1]);
                }
            }
        }
    }

    #pragma unroll
    for (int p = 0; p < 2; p++) {
        float aq[2][2][2];                       // [h][dy][dx]
        #pragma unroll
        for (int dy = 0; dy < 2; dy++)
            #pragma unroll
            for (int dx = 0; dx < 2; dx++) {
                float2 u = unpack2(acc[p][dy][dx]);
                aq[0][dy][dx] = u.x; aq[1][dy][dx] = u.y;
            }
        #pragma unroll
        for (int h = 0; h < 2; h++) {
            int oc = oc4 * 4 + p * 2 + h;
            float bias = b2[oc];
            float mx = -1e30f, ls = 0.f, lq = 0.f;
            #pragma unroll
            for (int dy = 0; dy < 2; dy++)
                #pragma unroll
                for (int dx = 0; dx < 2; dx++) {
                    float v = aq[h][dy][dx] + bias;
                    ls += v;
                    lq = fmaf(v, v, lq);
                    mx = fmaxf(mx, v);
                }
            g_pool2[((size_t)n * 64 + oc) * 16 + ty * 4 + tx] = mx;
            atomicAdd(&ssum[oc], ls);
            atomicAdd(&ssq[oc], lq);
        }
    }
    __syncthreads();
    if (tid < 64) { atomicAdd(&g_sum2[tid], ssum[tid]); atomicAdd(&g_sq2[tid], ssq[tid]); }
}

// ---------------- fc1: tiled SGEMM 128x64x16, A = relu(bn(pool2)) on load -----
// f32x2: acc pairs over m (A pairs free from LDS.128); B duplicated in SMEM,
// q-major permuted so the LDS.64 loads are bank-conflict-free.
__global__ __launch_bounds__(256) void fc1_kernel(const float* __restrict__ bf1) {
    __shared__ __align__(16) float As[16 * 132];  // [k][m], padded
    __shared__ __align__(16) ull Bsd[16 * 68];    // [k][q*16+tx] = (b,b)
    __shared__ float cs[64], cq[64];
    int tid = threadIdx.x;
    int m0 = blockIdx.x * 128, j0 = blockIdx.y * 64;
    int ty = tid >> 4, tx = tid & 15;
    if (tid < 64) { cs[tid] = 0.f; cq[tid] = 0.f; }

    ull cP[4][4];                                 // [m-pair][q], each = (m_lo,m_hi)
    #pragma unroll
    for (int r = 0; r < 4; r++)
        #pragma unroll
        for (int q = 0; q < 4; q++) cP[r][q] = 0ull;

    for (int kt = 0; kt < 64; kt++) {            // k-tile == channel (16 elems)
        float sc = g_a2[kt], sd = g_d2[kt];
        #pragma unroll
        for (int s = 0; s < 8; s++) {
            int idx = s * 256 + tid, ml = idx >> 4, kl = idx & 15;
            float raw = g_pool2[(size_t)(m0 + ml) * 1024 + kt * 16 + kl];
            As[kl * 132 + ml] = fmaxf(fmaf(sc, raw, sd), 0.f);
        }
        #pragma unroll
        for (int s = 0; s < 4; s++) {
            int idx = s * 256 + tid, jl = idx >> 4, kl = idx & 15;
            float v = g_qf1[(size_t)(j0 + jl) * 1024 + kt * 16 + kl];
            Bsd[kl * 68 + (jl & 3) * 16 + (jl >> 2)] = pack2(v, v);
        }
        __syncthreads();
        #pragma unroll
        for (int k = 0; k < 16; k++) {
            ulonglong2 aA = *reinterpret_cast<const ulonglong2*>(&As[k * 132 + ty * 8]);
            ulonglong2 aB = *reinterpret_cast<const ulonglong2*>(&As[k * 132 + ty * 8 + 4]);
            ull ap[4] = { aA.x, aA.y, aB.x, aB.y };   // (m0,m1)(m2,m3)(m4,m5)(m6,m7)
            ull bd[4];
            #pragma unroll
            for (int q = 0; q < 4; q++) bd[q] = Bsd[k * 68 + q * 16 + tx];
            #pragma unroll
            for (int r = 0; r < 4; r++)
                #pragma unroll
                for (int q = 0; q < 4; q++) cP[r][q] = ffma2(ap[r], bd[q], cP[r][q]);
        }
        __syncthreads();
    }

    float bias[4], ls[4] = {0, 0, 0, 0}, lq[4] = {0, 0, 0, 0};
    #pragma unroll
    for (int q = 0; q < 4; q++) bias[q] = bf1[j0 + tx * 4 + q];
    #pragma unroll
    for (int r2 = 0; r2 < 4; r2++) {
        #pragma unroll
        for (int q = 0; q < 4; q++) {
            float2 u = unpack2(cP[r2][q]);
            size_t row0 = (size_t)(m0 + ty * 8 + 2 * r2);
            float v0 = u.x + bias[q];
            g_z[row0 * 512 + j0 + tx * 4 + q] = v0;
            ls[q] += v0; lq[q] = fmaf(v0, v0, lq[q]);
            float v1 = u.y + bias[q];
            g_z[(row0 + 1) * 512 + j0 + tx * 4 + q] = v1;
            ls[q] += v1; lq[q] = fmaf(v1, v1, lq[q]);
        }
    }
    #pragma unroll
    for (int q = 0; q < 4; q++) { atomicAdd(&cs[tx * 4 + q], ls[q]); atomicAdd(&cq[tx * 4 + q], lq[q]); }
    __syncthreads();
    if (tid < 64) { atomicAdd(&g_sum3[j0 + tid], cs[tid]); atomicAdd(&g_sq3[j0 + tid], cq[tid]); }
}

// ---------------- fc2: [4096,512] x [512,10], one warp per row ----------------
__global__ __launch_bounds__(256) void fc2_kernel(const float* __restrict__ bf2,
                                                  float* __restrict__ out) {
    int w = threadIdx.x >> 5, l = threadIdx.x & 31;
    int row = blockIdx.x * 8 + w;
    const float* zr = g_z + (size_t)row * 512;
    float acc[10];
    #pragma unroll
    for (int k = 0; k < 10; k++) acc[k] = 0.f;
    for (int j = l; j < 512; j += 32) {
        float h = fmaxf(fmaf(g_a3[j], zr[j], g_d3[j]), 0.f);
        #pragma unroll
        for (int k = 0; k < 10; k++) acc[k] = fmaf(h, g_qf2[k * 512 + j], acc[k]);
    }
    #pragma unroll
    for (int k = 0; k < 10; k++)
        #pragma unroll
        for (int o = 16; o; o >>= 1) acc[k] += __shfl_xor_sync(0xffffffffu, acc[k], o);
    if (l < 10) out[row * 10 + l] = acc[l] + bf2[l];
}

// ---------------- host entry ----------------
extern "C" void kernel_launch(void* const* d_in, const int* in_sizes, int n_in,
                              void* d_out, int out_size) {
    const float* x   = (const float*)d_in[0];
    const float* w1  = (const float*)d_in[1];
    const float* b1  = (const float*)d_in[2];
    const float* g1  = (const float*)d_in[3];
    const float* be1 = (const float*)d_in[4];
    const float* w2  = (const float*)d_in[5];
    const float* b2  = (const float*)d_in[6];
    const float* g2  = (const float*)d_in[7];
    const float* be2 = (const float*)d_in[8];
    const float* wf1 = (const float*)d_in[9];
    const float* bf1 = (const float*)d_in[10];
    const float* g3  = (const float*)d_in[11];
    const float* be3 = (const float*)d_in[12];
    const float* wf2 = (const float*)d_in[13];
    const float* bf2 = (const float*)d_in[14];
    float* out = (float*)d_out;

    // dynamic smem opt-in for conv2 (>48KB); host-side attr, capture-safe
    cudaFuncSetAttribute(conv2_kernel,
                         cudaFuncAttributeMaxDynamicSharedMemorySize, CONV2_DSMEM);

    zero_stats_kernel<<<1, 512>>>();

    // maxabs reductions (grid-wide, deterministic atomicMax on uint bits)
    maxabs_kernel<<<1,   256>>>(w1,  800,    0);
    maxabs_kernel<<<32,  256>>>(w2,  51200,  1);
    maxabs_kernel<<<256, 256>>>(wf1, 524288, 2);
    maxabs_kernel<<<4,   256>>>(wf2, 5120,   3);

    // quantize passes (fully parallel)
    quantize_kernel<<<4,    256>>>(w1,  800,    0);
    quantize_w2_kernel<<<200, 256>>>(w2);
    quantize_kernel<<<2048, 256>>>(wf1, 524288, 2);
    quantize_kernel<<<20,   256>>>(wf2, 5120,   3);

    conv1_kernel<<<NIMG, 256>>>(x, b1);
    finalize_kernel<<<1, 32>>>(g1, be1, 0);

    conv2_kernel<<<NIMG, 256, CONV2_DSMEM>>>(b2);
    finalize_kernel<<<1, 64>>>(g2, be2, 1);

    fc1_kernel<<<dim3(32, 8), 256>>>(bf1);
    finalize_kernel<<<2, 256>>>(g3, be3, 2);

    fc2_kernel<<<512, 256>>>(bf2, out);
}

// round 10
// speedup vs baseline: 1.8277x; 1.8277x over previous
#include <cuda_runtime.h>
#include <cuda_bf16.h>
#include <math.h>
#include <string.h>

// ============================================================================
// MNIST_CNN2D_TWN forward pass. R9: conv2 on mma.sync bf16 tensor cores
// (m16n8k16, hi/lo input split, f32 accum). tcgen05 is unusable here: the
// harness builds PTX at compute_103 (no 'a'), where ptxas rejects tcgen05.
// conv1/fc1/fc2 remain the proven R6 scalar versions.
// ============================================================================

#define NIMG 4096

// ---------------- device scratch (static; no allocation) ----------------
__device__ float g_q1[800];                        // [32][25] ternary
__device__ __align__(16) __nv_bfloat16 g_q2bf[65536]; // [ic=32][oc=64][tap=32] bf16 (tap>=25 -> 0)
__device__ float g_qf1[524288];                    // [512][1024] ternary
__device__ float g_qf2[5120];                      // [10][512] ternary
__device__ float g_pool1[(size_t)NIMG * 32 * 144]; // raw pooled conv1 (pre-bn)
__device__ float g_pool2[(size_t)NIMG * 64 * 16];  // raw pooled conv2 (pre-bn)
__device__ float g_z[(size_t)NIMG * 512];          // fc1 pre-bn output
__device__ float g_sum1[32], g_sq1[32], g_a1[32], g_d1[32];
__device__ float g_sum2[64], g_sq2[64], g_a2[64], g_d2[64];
__device__ float g_sum3[512], g_sq3[512], g_a3[512], g_d3[512];
__device__ unsigned g_tmax[4];                     // maxabs bits (w1,w2,wf1,wf2)

// ---------------- mma.sync wrapper (sm_80+ PTX, safe on compute_103) --------
__device__ __forceinline__ void mma_bf16(float* d,
                                         unsigned a0, unsigned a1, unsigned a2, unsigned a3,
                                         unsigned b0, unsigned b1) {
    asm volatile(
        "mma.sync.aligned.m16n8k16.row.col.f32.bf16.bf16.f32 "
        "{%0,%1,%2,%3}, {%4,%5,%6,%7}, {%8,%9}, {%0,%1,%2,%3};"
        : "+f"(d[0]), "+f"(d[1]), "+f"(d[2]), "+f"(d[3])
        : "r"(a0), "r"(a1), "r"(a2), "r"(a3), "r"(b0), "r"(b1));
}

// ---------------- stats zeroing ----------------
__global__ void zero_stats_kernel() {
    int i = threadIdx.x;
    if (i < 32) { g_sum1[i] = 0.f; g_sq1[i] = 0.f; }
    if (i < 64) { g_sum2[i] = 0.f; g_sq2[i] = 0.f; }
    if (i < 4)  { g_tmax[i] = 0u; }
    for (int j = i; j < 512; j += blockDim.x) { g_sum3[j] = 0.f; g_sq3[j] = 0.f; }
}

// ---------------- grid-wide maxabs reduction ----------------
__global__ void maxabs_kernel(const float* __restrict__ w, int n, int which) {
    __shared__ float red[8];
    int tid = threadIdx.x;
    float m = 0.f;
    for (int i = blockIdx.x * blockDim.x + tid; i < n; i += gridDim.x * blockDim.x)
        m = fmaxf(m, fabsf(w[i]));
    #pragma unroll
    for (int o = 16; o; o >>= 1) m = fmaxf(m, __shfl_xor_sync(0xffffffffu, m, o));
    if ((tid & 31) == 0) red[tid >> 5] = m;
    __syncthreads();
    if (tid < 32) {
        float v = (tid < (int)(blockDim.x >> 5)) ? red[tid] : 0.f;
        #pragma unroll
        for (int o = 4; o; o >>= 1) v = fmaxf(v, __shfl_xor_sync(0xffffffffu, v, o));
        if (tid == 0) atomicMax(&g_tmax[which], __float_as_uint(v));
    }
}

// which: 0 -> g_q1 (n=800), 2 -> g_qf1, 3 -> g_qf2
__global__ void quantize_kernel(const float* __restrict__ w, int n, int which) {
    float t = 0.05f * __uint_as_float(g_tmax[which]);
    float* q = (which == 0) ? g_q1 : (which == 2) ? g_qf1 : g_qf2;
    int i = blockIdx.x * blockDim.x + threadIdx.x;
    if (i < n) {
        float v = w[i];
        q[i] = (v > t ? 1.f : 0.f) - (v < -t ? 1.f : 0.f);
    }
}

// w2 [oc=64][ic=32][5][5] -> g_q2bf[ic][oc][tap32] bf16 (ternary, pad 0)
__global__ void quantize_w2_kernel(const float* __restrict__ w) {
    float t = 0.05f * __uint_as_float(g_tmax[1]);
    int idx = blockIdx.x * blockDim.x + threadIdx.x;
    if (idx >= 65536) return;
    int ic = idx >> 11, oc = (idx >> 5) & 63, tap = idx & 31;
    float val = 0.f;
    if (tap < 25) {
        float wv = w[oc * 800 + ic * 25 + tap];
        val = (wv > t ? 1.f : 0.f) - (wv < -t ? 1.f : 0.f);
    }
    g_q2bf[idx] = __float2bfloat16(val);
}

// ---------------- bn affine finalize ----------------
__global__ void finalize_kernel(const float* __restrict__ gam,
                                const float* __restrict__ bet, int which) {
    const float* sum; const float* sq; float* a; float* d; int C; float inv;
    if (which == 0)      { sum = g_sum1; sq = g_sq1; a = g_a1; d = g_d1; C = 32;  inv = 1.f / 2359296.f; }
    else if (which == 1) { sum = g_sum2; sq = g_sq2; a = g_a2; d = g_d2; C = 64;  inv = 1.f / 262144.f;  }
    else                 { sum = g_sum3; sq = g_sq3; a = g_a3; d = g_d3; C = 512; inv = 1.f / 4096.f;    }
    int i = blockIdx.x * blockDim.x + threadIdx.x;
    if (i < C) {
        float m = sum[i] * inv;
        float v = sq[i] * inv - m * m;
        float ai = gam[i] / sqrtf(v + 1e-5f);
        a[i] = ai;
        d[i] = bet[i] - m * ai;
    }
}

// ---------------- conv1 (R6 scalar): 1->32, 5x5, bias+stats+maxpool2 --------
__global__ __launch_bounds__(256) void conv1_kernel(const float* __restrict__ x,
                                                    const float* __restrict__ b1) {
    __shared__ float img[784];
    __shared__ float wsh[800];
    __shared__ float ssum[32], ssq[32];
    int n = blockIdx.x, tid = threadIdx.x;

    for (int i = tid; i < 784; i += 256) img[i] = x[(size_t)n * 784 + i];
    for (int i = tid; i < 800; i += 256) wsh[i] = g_q1[i];
    if (tid < 32) { ssum[tid] = 0.f; ssq[tid] = 0.f; }
    __syncthreads();

    int c = tid >> 3, sub = tid & 7;
    float wr[25];
    #pragma unroll
    for (int k = 0; k < 25; k++) wr[k] = wsh[c * 25 + k];
    float bias = b1[c];
    float lsum = 0.f, lsq = 0.f;
    float* outp = g_pool1 + ((size_t)n * 32 + c) * 144;

    for (int k2 = 0; k2 < 18; k2++) {
        int p = sub * 18 + k2;
        int py = p / 12, px = p - py * 12;
        int oy = 2 * py, ox = 2 * px;
        float win[36];
        #pragma unroll
        for (int r = 0; r < 6; r++)
            #pragma unroll
            for (int cc = 0; cc < 6; cc++)
                win[r * 6 + cc] = img[(oy + r) * 28 + ox + cc];
        float mx = -1e30f;
        #pragma unroll
        for (int dy = 0; dy < 2; dy++)
            #pragma unroll
            for (int dx = 0; dx < 2; dx++) {
                float acc = bias;
                #pragma unroll
                for (int ky = 0; ky < 5; ky++)
                    #pragma unroll
                    for (int kx = 0; kx < 5; kx++)
                        acc = fmaf(win[(dy + ky) * 6 + dx + kx], wr[ky * 5 + kx], acc);
                lsum += acc;
                lsq = fmaf(acc, acc, lsq);
                mx = fmaxf(mx, acc);
            }
        outp[p] = mx;
    }
    atomicAdd(&ssum[c], lsum);
    atomicAdd(&ssq[c], lsq);
    __syncthreads();
    if (tid < 32) { atomicAdd(&g_sum1[tid], ssum[tid]); atomicAdd(&g_sq1[tid], ssq[tid]); }
}

// ---------------- conv2 on mma.sync (hi/lo bf16 split) ----------------------
// Per CTA: 2 images. M=128 (img*64 + y*8 + x), N=64 oc, per-ic K chunks of 32.
// Warp w: m_w=(w>>1)*32, n_w=(w&1)*32 -> 32x32 tile = 2x4 m16n8 mma tiles.
// Dynamic smem layout (bytes):
//   [0]     ssum[64]           (256)
//   [256]   ssq[64]            (256)
//   [512]   ish  9216 f32      (36864)  -- reused as Ds[128][65] f32 after MMAs
//   [37376] A_hi 128x40 bf16   (10240)
//   [47616] A_lo 128x40 bf16   (10240)
//   [57856] Bs    64x40 bf16   (5120)   -> total 62976
#define C2_DSM 62976

__global__ __launch_bounds__(256) void conv2_mma_kernel(const float* __restrict__ b2) {
    extern __shared__ __align__(16) unsigned char dynsm[];
    float* ssum = (float*)dynsm;
    float* ssq  = (float*)(dynsm + 256);
    float* ish  = (float*)(dynsm + 512);
    float* Ds   = ish;                                   // reuse (stride 65)
    __nv_bfloat16* Ah = (__nv_bfloat16*)(dynsm + 37376);
    __nv_bfloat16* Al = (__nv_bfloat16*)(dynsm + 47616);
    __nv_bfloat16* Bs = (__nv_bfloat16*)(dynsm + 57856);

    int tid = threadIdx.x, lane = tid & 31, w = tid >> 5;
    int n0 = blockIdx.x * 2;
    if (tid < 64) { ssum[tid] = 0.f; ssq[tid] = 0.f; }

    // stage bn1+relu inputs for 2 images (2304 float4)
    {
        const float4* src = (const float4*)(g_pool1 + (size_t)n0 * 4608);
        for (int i = tid; i < 2304; i += 256) {
            int c = (i / 36) & 31;
            float a = g_a1[c], d = g_d1[c];
            float4 r = src[i];
            float4 v;
            v.x = fmaxf(fmaf(a, r.x, d), 0.f);
            v.y = fmaxf(fmaf(a, r.y, d), 0.f);
            v.z = fmaxf(fmaf(a, r.z, d), 0.f);
            v.w = fmaxf(fmaf(a, r.w, d), 0.f);
            ((float4*)ish)[i] = v;
        }
    }

    int g = lane >> 2, tig = lane & 3;
    int m_w = (w >> 1) * 32, n_w = (w & 1) * 32;
    float acc[2][4][4];
    #pragma unroll
    for (int mt = 0; mt < 2; mt++)
        #pragma unroll
        for (int nt = 0; nt < 4; nt++)
            #pragma unroll
            for (int q = 0; q < 4; q++) acc[mt][nt][q] = 0.f;

    // im2col mapping: thread -> (row = tid>>1, tap half = tid&1)
    int arow = tid >> 1, ahalf = tid & 1;
    int aimg = arow >> 6, apos = arow & 63, ay = apos >> 3, ax = apos & 7;
    int abase = aimg * 4608 + ay * 12 + ax;

    for (int ic = 0; ic < 32; ic++) {
        __syncthreads();                       // prev MMAs done reading A/B
        // B chunk: flat vector copy of prebaked [64][32] bf16 into stride-40 rows
        {
            uint4 v = ((const uint4*)(g_q2bf + ic * 2048))[tid];
            int nn = tid >> 2, kp = tid & 3;   // 8 bf16 per uint4
            *(uint4*)(Bs + nn * 40 + kp * 8) = v;
        }
        // A chunk: im2col + hi/lo bf16 split, 16 taps per thread
        {
            int base = abase + ic * 144;
            int tb = ahalf * 16;
            #pragma unroll
            for (int j = 0; j < 8; j++) {
                int t0 = tb + 2 * j, t1 = t0 + 1;
                float v0 = (t0 < 25) ? ish[base + (t0 / 5) * 12 + (t0 % 5)] : 0.f;
                float v1 = (t1 < 25) ? ish[base + (t1 / 5) * 12 + (t1 % 5)] : 0.f;
                __nv_bfloat162 h = __floats2bfloat162_rn(v0, v1);
                float2 hf = __bfloat1622float2(h);
                __nv_bfloat162 l = __floats2bfloat162_rn(v0 - hf.x, v1 - hf.y);
                *(__nv_bfloat162*)(Ah + arow * 40 + t0) = h;
                *(__nv_bfloat162*)(Al + arow * 40 + t0) = l;
            }
        }
        __syncthreads();
        // MMA: 2 k-steps x {hi,lo} x 2 m-tiles x 4 n-tiles
        #pragma unroll
        for (int ks = 0; ks < 2; ks++) {
            int k0 = ks * 16;
            unsigned b0[4], b1[4];
            #pragma unroll
            for (int nt = 0; nt < 4; nt++) {
                const __nv_bfloat16* bp = Bs + (n_w + nt * 8 + g) * 40 + k0 + tig * 2;
                b0[nt] = *(const unsigned*)bp;
                b1[nt] = *(const unsigned*)(bp + 8);
            }
            #pragma unroll
            for (int var = 0; var < 2; var++) {
                const __nv_bfloat16* Ab = var ? Al : Ah;
                #pragma unroll
                for (int mt = 0; mt < 2; mt++) {
                    const __nv_bfloat16* ap = Ab + (m_w + mt * 16 + g) * 40 + k0 + tig * 2;
                    unsigned a0 = *(const unsigned*)ap;
                    unsigned a1 = *(const unsigned*)(ap + 8 * 40);
                    unsigned a2 = *(const unsigned*)(ap + 8);
                    unsigned a3 = *(const unsigned*)(ap + 8 * 40 + 8);
                    #pragma unroll
                    for (int nt = 0; nt < 4; nt++)
                        mma_bf16(acc[mt][nt], a0, a1, a2, a3, b0[nt], b1[nt]);
                }
            }
        }
    }
    __syncthreads();                            // all MMAs done; safe to reuse ish

    // write D fragments to Ds[128][65]
    #pragma unroll
    for (int mt = 0; mt < 2; mt++)
        #pragma unroll
        for (int nt = 0; nt < 4; nt++) {
            int r0 = m_w + mt * 16 + g, c0 = n_w + nt * 8 + tig * 2;
            Ds[r0 * 65 + c0]       = acc[mt][nt][0];
            Ds[r0 * 65 + c0 + 1]   = acc[mt][nt][1];
            Ds[(r0 + 8) * 65 + c0]     = acc[mt][nt][2];
            Ds[(r0 + 8) * 65 + c0 + 1] = acc[mt][nt][3];
        }
    __syncthreads();

    // bias + stats + maxpool: threads 0..127 = (img, oc)
    if (tid < 128) {
        int oc = tid & 63, im = tid >> 6;
        float bias = b2[oc];
        float ls = 0.f, lq = 0.f;
        #pragma unroll
        for (int py = 0; py < 4; py++)
            #pragma unroll
            for (int px = 0; px < 4; px++) {
                int r = im * 64 + py * 16 + px * 2;
                float v0 = Ds[r * 65 + oc] + bias;
                float v1 = Ds[(r + 1) * 65 + oc] + bias;
                float v2 = Ds[(r + 8) * 65 + oc] + bias;
                float v3 = Ds[(r + 9) * 65 + oc] + bias;
                ls += v0 + v1 + v2 + v3;
                lq = fmaf(v0, v0, lq); lq = fmaf(v1, v1, lq);
                lq = fmaf(v2, v2, lq); lq = fmaf(v3, v3, lq);
                float mx = fmaxf(fmaxf(v0, v1), fmaxf(v2, v3));
                g_pool2[((size_t)(n0 + im) * 64 + oc) * 16 + py * 4 + px] = mx;
            }
        atomicAdd(&ssum[oc], ls);
        atomicAdd(&ssq[oc], lq);
    }
    __syncthreads();
    if (tid < 64) { atomicAdd(&g_sum2[tid], ssum[tid]); atomicAdd(&g_sq2[tid], ssq[tid]); }
}

// ---------------- fc1 (R6 scalar): tiled SGEMM 128x64x16 --------------------
__global__ __launch_bounds__(256) void fc1_kernel(const float* __restrict__ bf1) {
    __shared__ __align__(16) float As[16 * 132];
    __shared__ __align__(16) float Bs[16 * 68];
    __shared__ float cs[64], cq[64];
    int tid = threadIdx.x;
    int m0 = blockIdx.x * 128, j0 = blockIdx.y * 64;
    int ty = tid >> 4, tx = tid & 15;
    if (tid < 64) { cs[tid] = 0.f; cq[tid] = 0.f; }

    float c[8][4];
    #pragma unroll
    for (int r = 0; r < 8; r++)
        #pragma unroll
        for (int q = 0; q < 4; q++) c[r][q] = 0.f;

    for (int kt = 0; kt < 64; kt++) {
        float sc = g_a2[kt], sd = g_d2[kt];
        #pragma unroll
        for (int s = 0; s < 8; s++) {
            int idx = s * 256 + tid, ml = idx >> 4, kl = idx & 15;
            float raw = g_pool2[(size_t)(m0 + ml) * 1024 + kt * 16 + kl];
            As[kl * 132 + ml] = fmaxf(fmaf(sc, raw, sd), 0.f);
        }
        #pragma unroll
        for (int s = 0; s < 4; s++) {
            int idx = s * 256 + tid, jl = idx >> 4, kl = idx & 15;
            Bs[kl * 68 + jl] = g_qf1[(size_t)(j0 + jl) * 1024 + kt * 16 + kl];
        }
        __syncthreads();
        #pragma unroll
        for (int k = 0; k < 16; k++) {
            float4 a0 = *reinterpret_cast<const float4*>(&As[k * 132 + ty * 8]);
            float4 a1 = *reinterpret_cast<const float4*>(&As[k * 132 + ty * 8 + 4]);
            float4 b  = *reinterpret_cast<const float4*>(&Bs[k * 68 + tx * 4]);
            float av[8] = {a0.x, a0.y, a0.z, a0.w, a1.x, a1.y, a1.z, a1.w};
            float bv[4] = {b.x, b.y, b.z, b.w};
            #pragma unroll
            for (int r = 0; r < 8; r++)
                #pragma unroll
                for (int q = 0; q < 4; q++) c[r][q] = fmaf(av[r], bv[q], c[r][q]);
        }
        __syncthreads();
    }

    float bias[4], ls[4] = {0, 0, 0, 0}, lq[4] = {0, 0, 0, 0};
    #pragma unroll
    for (int q = 0; q < 4; q++) bias[q] = bf1[j0 + tx * 4 + q];
    #pragma unroll
    for (int r = 0; r < 8; r++) {
        size_t row = (size_t)(m0 + ty * 8 + r);
        #pragma unroll
        for (int q = 0; q < 4; q++) {
            float v = c[r][q] + bias[q];
            g_z[row * 512 + j0 + tx * 4 + q] = v;
            ls[q] += v;
            lq[q] = fmaf(v, v, lq[q]);
        }
    }
    #pragma unroll
    for (int q = 0; q < 4; q++) { atomicAdd(&cs[tx * 4 + q], ls[q]); atomicAdd(&cq[tx * 4 + q], lq[q]); }
    __syncthreads();
    if (tid < 64) { atomicAdd(&g_sum3[j0 + tid], cs[tid]); atomicAdd(&g_sq3[j0 + tid], cq[tid]); }
}

// ---------------- fc2: [4096,512] x [512,10], one warp per row ----------------
__global__ __launch_bounds__(256) void fc2_kernel(const float* __restrict__ bf2,
                                                  float* __restrict__ out) {
    int w = threadIdx.x >> 5, l = threadIdx.x & 31;
    int row = blockIdx.x * 8 + w;
    const float* zr = g_z + (size_t)row * 512;
    float acc[10];
    #pragma unroll
    for (int k = 0; k < 10; k++) acc[k] = 0.f;
    for (int j = l; j < 512; j += 32) {
        float h = fmaxf(fmaf(g_a3[j], zr[j], g_d3[j]), 0.f);
        #pragma unroll
        for (int k = 0; k < 10; k++) acc[k] = fmaf(h, g_qf2[k * 512 + j], acc[k]);
    }
    #pragma unroll
    for (int k = 0; k < 10; k++)
        #pragma unroll
        for (int o = 16; o; o >>= 1) acc[k] += __shfl_xor_sync(0xffffffffu, acc[k], o);
    if (l < 10) out[row * 10 + l] = acc[l] + bf2[l];
}

// ---------------- host entry ----------------
extern "C" void kernel_launch(void* const* d_in, const int* in_sizes, int n_in,
                              void* d_out, int out_size) {
    const float* x   = (const float*)d_in[0];
    const float* w1  = (const float*)d_in[1];
    const float* b1  = (const float*)d_in[2];
    const float* g1  = (const float*)d_in[3];
    const float* be1 = (const float*)d_in[4];
    const float* w2  = (const float*)d_in[5];
    const float* b2  = (const float*)d_in[6];
    const float* g2  = (const float*)d_in[7];
    const float* be2 = (const float*)d_in[8];
    const float* wf1 = (const float*)d_in[9];
    const float* bf1 = (const float*)d_in[10];
    const float* g3  = (const float*)d_in[11];
    const float* be3 = (const float*)d_in[12];
    const float* wf2 = (const float*)d_in[13];
    const float* bf2 = (const float*)d_in[14];
    float* out = (float*)d_out;

    cudaFuncSetAttribute(conv2_mma_kernel,
                         cudaFuncAttributeMaxDynamicSharedMemorySize, C2_DSM);

    zero_stats_kernel<<<1, 512>>>();

    maxabs_kernel<<<1,   256>>>(w1,  800,    0);
    maxabs_kernel<<<32,  256>>>(w2,  51200,  1);
    maxabs_kernel<<<256, 256>>>(wf1, 524288, 2);
    maxabs_kernel<<<4,   256>>>(wf2, 5120,   3);

    quantize_kernel<<<4,    256>>>(w1,  800,    0);
    quantize_w2_kernel<<<256, 256>>>(w2);
    quantize_kernel<<<2048, 256>>>(wf1, 524288, 2);
    quantize_kernel<<<20,   256>>>(wf2, 5120,   3);

    conv1_kernel<<<NIMG, 256>>>(x, b1);
    finalize_kernel<<<1, 32>>>(g1, be1, 0);

    conv2_mma_kernel<<<NIMG / 2, 256, C2_DSM>>>(b2);
    finalize_kernel<<<1, 64>>>(g2, be2, 1);

    fc1_kernel<<<dim3(32, 8), 256>>>(bf1);
    finalize_kernel<<<2, 256>>>(g3, be3, 2);

    fc2_kernel<<<512, 256>>>(bf2, out);
}

// round 14
// speedup vs baseline: 2.1130x; 1.1561x over previous
#include <cuda_runtime.h>
#include <cuda_bf16.h>
#include <math.h>
#include <string.h>

// ============================================================================
// MNIST_CNN2D_TWN forward pass. R10:
//  - conv2: pre-split bn1+relu inputs into bf16 hi/lo ONCE (kills ~11x im2col
//    convert redundancy), double-buffered A/B chunks (1 sync/ic), compile-time
//    tap offsets (ahalf = tid>>7).
//  - fc1: ported to mma.sync bf16 hi/lo (128x128 tile, K-chunks of 32),
//    qf1 prebaked to bf16 (ternary exact in bf16).
// conv1/fc2 remain R6 scalar. tcgen05 unusable (harness targets compute_103).
// ============================================================================

#define NIMG 4096

// ---------------- mma.sync wrapper (sm_80+ PTX, safe on compute_103) --------
__device__ __forceinline__ void mma_bf16(float* d,
                                         unsigned a0, unsigned a1, unsigned a2, unsigned a3,
                                         unsigned b0, unsigned b1) {
    asm volatile(
        "mma.sync.aligned.m16n8k16.row.col.f32.bf16.bf16.f32 "
        "{%0,%1,%2,%3}, {%4,%5,%6,%7}, {%8,%9}, {%0,%1,%2,%3};"
        : "+f"(d[0]), "+f"(d[1]), "+f"(d[2]), "+f"(d[3])
        : "r"(a0), "r"(a1), "r"(a2), "r"(a3), "r"(b0), "r"(b1));
}

// ---------------- device scratch (static; no allocation) ----------------
__device__ float g_q1[800];                           // [32][25] ternary
__device__ __align__(16) __nv_bfloat16 g_q2bf[65536]; // [ic=32][oc=64][tap=32] bf16
__device__ __align__(16) __nv_bfloat16 g_qf1b[524288];// [512][1024] ternary bf16
__device__ float g_qf2[5120];                         // [10][512] ternary
__device__ float g_pool1[(size_t)NIMG * 32 * 144];    // raw pooled conv1 (pre-bn)
__device__ float g_pool2[(size_t)NIMG * 64 * 16];     // raw pooled conv2 (pre-bn)
__device__ float g_z[(size_t)NIMG * 512];             // fc1 pre-bn output
__device__ float g_sum1[32], g_sq1[32], g_a1[32], g_d1[32];
__device__ float g_sum2[64], g_sq2[64], g_a2[64], g_d2[64];
__device__ float g_sum3[512], g_sq3[512], g_a3[512], g_d3[512];
__device__ unsigned g_tmax[4];                        // maxabs bits (w1,w2,wf1,wf2)

// ---------------- stats zeroing ----------------
__global__ void zero_stats_kernel() {
    int i = threadIdx.x;
    if (i < 32) { g_sum1[i] = 0.f; g_sq1[i] = 0.f; }
    if (i < 64) { g_sum2[i] = 0.f; g_sq2[i] = 0.f; }
    if (i < 4)  { g_tmax[i] = 0u; }
    for (int j = i; j < 512; j += blockDim.x) { g_sum3[j] = 0.f; g_sq3[j] = 0.f; }
}

// ---------------- grid-wide maxabs reduction ----------------
__global__ void maxabs_kernel(const float* __restrict__ w, int n, int which) {
    __shared__ float red[8];
    int tid = threadIdx.x;
    float m = 0.f;
    for (int i = blockIdx.x * blockDim.x + tid; i < n; i += gridDim.x * blockDim.x)
        m = fmaxf(m, fabsf(w[i]));
    #pragma unroll
    for (int o = 16; o; o >>= 1) m = fmaxf(m, __shfl_xor_sync(0xffffffffu, m, o));
    if ((tid & 31) == 0) red[tid >> 5] = m;
    __syncthreads();
    if (tid < 32) {
        float v = (tid < (int)(blockDim.x >> 5)) ? red[tid] : 0.f;
        #pragma unroll
        for (int o = 4; o; o >>= 1) v = fmaxf(v, __shfl_xor_sync(0xffffffffu, v, o));
        if (tid == 0) atomicMax(&g_tmax[which], __float_as_uint(v));
    }
}

// which: 0 -> g_q1 f32, 2 -> g_qf1b bf16, 3 -> g_qf2 f32
__global__ void quantize_kernel(const float* __restrict__ w, int n, int which) {
    float t = 0.05f * __uint_as_float(g_tmax[which]);
    int i = blockIdx.x * blockDim.x + threadIdx.x;
    if (i >= n) return;
    float v = w[i];
    float qv = (v > t ? 1.f : 0.f) - (v < -t ? 1.f : 0.f);
    if (which == 2)      g_qf1b[i] = __float2bfloat16(qv);
    else if (which == 0) g_q1[i] = qv;
    else                 g_qf2[i] = qv;
}

// w2 [oc=64][ic=32][5][5] -> g_q2bf[ic][oc][tap32] bf16 (ternary, pad 0)
__global__ void quantize_w2_kernel(const float* __restrict__ w) {
    float t = 0.05f * __uint_as_float(g_tmax[1]);
    int idx = blockIdx.x * blockDim.x + threadIdx.x;
    if (idx >= 65536) return;
    int ic = idx >> 11, oc = (idx >> 5) & 63, tap = idx & 31;
    float val = 0.f;
    if (tap < 25) {
        float wv = w[oc * 800 + ic * 25 + tap];
        val = (wv > t ? 1.f : 0.f) - (wv < -t ? 1.f : 0.f);
    }
    g_q2bf[idx] = __float2bfloat16(val);
}

// ---------------- bn affine finalize ----------------
__global__ void finalize_kernel(const float* __restrict__ gam,
                                const float* __restrict__ bet, int which) {
    const float* sum; const float* sq; float* a; float* d; int C; float inv;
    if (which == 0)      { sum = g_sum1; sq = g_sq1; a = g_a1; d = g_d1; C = 32;  inv = 1.f / 2359296.f; }
    else if (which == 1) { sum = g_sum2; sq = g_sq2; a = g_a2; d = g_d2; C = 64;  inv = 1.f / 262144.f;  }
    else                 { sum = g_sum3; sq = g_sq3; a = g_a3; d = g_d3; C = 512; inv = 1.f / 4096.f;    }
    int i = blockIdx.x * blockDim.x + threadIdx.x;
    if (i < C) {
        float m = sum[i] * inv;
        float v = sq[i] * inv - m * m;
        float ai = gam[i] / sqrtf(v + 1e-5f);
        a[i] = ai;
        d[i] = bet[i] - m * ai;
    }
}

// ---------------- conv1 (R6 scalar): 1->32, 5x5, bias+stats+maxpool2 --------
__global__ __launch_bounds__(256) void conv1_kernel(const float* __restrict__ x,
                                                    const float* __restrict__ b1) {
    __shared__ float img[784];
    __shared__ float wsh[800];
    __shared__ float ssum[32], ssq[32];
    int n = blockIdx.x, tid = threadIdx.x;

    for (int i = tid; i < 784; i += 256) img[i] = x[(size_t)n * 784 + i];
    for (int i = tid; i < 800; i += 256) wsh[i] = g_q1[i];
    if (tid < 32) { ssum[tid] = 0.f; ssq[tid] = 0.f; }
    __syncthreads();

    int c = tid >> 3, sub = tid & 7;
    float wr[25];
    #pragma unroll
    for (int k = 0; k < 25; k++) wr[k] = wsh[c * 25 + k];
    float bias = b1[c];
    float lsum = 0.f, lsq = 0.f;
    float* outp = g_pool1 + ((size_t)n * 32 + c) * 144;

    for (int k2 = 0; k2 < 18; k2++) {
        int p = sub * 18 + k2;
        int py = p / 12, px = p - py * 12;
        int oy = 2 * py, ox = 2 * px;
        float win[36];
        #pragma unroll
        for (int r = 0; r < 6; r++)
            #pragma unroll
            for (int cc = 0; cc < 6; cc++)
                win[r * 6 + cc] = img[(oy + r) * 28 + ox + cc];
        float mx = -1e30f;
        #pragma unroll
        for (int dy = 0; dy < 2; dy++)
            #pragma unroll
            for (int dx = 0; dx < 2; dx++) {
                float acc = bias;
                #pragma unroll
                for (int ky = 0; ky < 5; ky++)
                    #pragma unroll
                    for (int kx = 0; kx < 5; kx++)
                        acc = fmaf(win[(dy + ky) * 6 + dx + kx], wr[ky * 5 + kx], acc);
                lsum += acc;
                lsq = fmaf(acc, acc, lsq);
                mx = fmaxf(mx, acc);
            }
        outp[p] = mx;
    }
    atomicAdd(&ssum[c], lsum);
    atomicAdd(&ssq[c], lsq);
    __syncthreads();
    if (tid < 32) { atomicAdd(&g_sum1[tid], ssum[tid]); atomicAdd(&g_sq1[tid], ssq[tid]); }
}

// ---------------- conv2 on mma.sync: pre-split hi/lo + double buffer --------
// Per CTA: 2 images. M=128 (img*64 + y*8 + x), N=64 oc, per-ic K chunks of 32.
// Dynamic smem layout (bytes):
//   [0]     ssum[64] (256)   [256] ssq[64] (256)
//   [512]   ish_hi bf16[9216] (18432)   -- [img][ic][144]
//   [18944] ish_lo bf16[9216] (18432)   -- region [512..37376) reused as Ds[128][65] f32
//   [37376] buf0: Ah 10240 | Al 10240 | Bs 5120   (25600)
//   [62976] buf1: same                            (25600)  -> total 88576
#define C2_DSM 88576

__global__ __launch_bounds__(256) void conv2_mma_kernel(const float* __restrict__ b2) {
    extern __shared__ __align__(16) unsigned char dynsm[];
    float* ssum = (float*)dynsm;
    float* ssq  = (float*)(dynsm + 256);
    unsigned short* ishh = (unsigned short*)(dynsm + 512);
    unsigned short* ishl = (unsigned short*)(dynsm + 18944);
    float* Ds = (float*)(dynsm + 512);                 // reuse, stride 65

    int tid = threadIdx.x, lane = tid & 31, w = tid >> 5;
    int n0 = blockIdx.x * 2;
    if (tid < 64) { ssum[tid] = 0.f; ssq[tid] = 0.f; }

    // stage bn1+relu, split hi/lo ONCE (2304 float4 = 9216 elems)
    {
        const float4* src = (const float4*)(g_pool1 + (size_t)n0 * 4608);
        for (int i = tid; i < 2304; i += 256) {
            int c = (i / 36) & 31;
            float a = g_a1[c], d = g_d1[c];
            float4 r = src[i];
            float v0 = fmaxf(fmaf(a, r.x, d), 0.f);
            float v1 = fmaxf(fmaf(a, r.y, d), 0.f);
            float v2 = fmaxf(fmaf(a, r.z, d), 0.f);
            float v3 = fmaxf(fmaf(a, r.w, d), 0.f);
            __nv_bfloat162 h01 = __floats2bfloat162_rn(v0, v1);
            __nv_bfloat162 h23 = __floats2bfloat162_rn(v2, v3);
            float2 f01 = __bfloat1622float2(h01);
            float2 f23 = __bfloat1622float2(h23);
            __nv_bfloat162 l01 = __floats2bfloat162_rn(v0 - f01.x, v1 - f01.y);
            __nv_bfloat162 l23 = __floats2bfloat162_rn(v2 - f23.x, v3 - f23.y);
            ((__nv_bfloat162*)ishh)[2 * i]     = h01;
            ((__nv_bfloat162*)ishh)[2 * i + 1] = h23;
            ((__nv_bfloat162*)ishl)[2 * i]     = l01;
            ((__nv_bfloat162*)ishl)[2 * i + 1] = l23;
        }
    }
    __syncthreads();

    int g = lane >> 2, tig = lane & 3;
    int m_w = (w >> 1) * 32, n_w = (w & 1) * 32;
    float acc[2][4][4];
    #pragma unroll
    for (int mt = 0; mt < 2; mt++)
        #pragma unroll
        for (int nt = 0; nt < 4; nt++)
            #pragma unroll
            for (int q = 0; q < 4; q++) acc[mt][nt][q] = 0.f;

    // A build mapping: arow = tid&127, ahalf = tid>>7 (warp-uniform -> const taps)
    int arow = tid & 127, ahalf = tid >> 7;
    int aimg = arow >> 6, apos = arow & 63, ay = apos >> 3, ax = apos & 7;
    int abase0 = aimg * 4608 + ay * 12 + ax;

    for (int ic = 0; ic < 32; ic++) {
        unsigned boff = (unsigned)(ic & 1) * 25600u;
        unsigned char* Ahb = dynsm + 37376 + boff;
        unsigned char* Alb = Ahb + 10240;
        unsigned char* Bsb = Ahb + 20480;

        // B fill: flat copy of prebaked [64][32] bf16 into stride-40 rows
        {
            uint4 v = ((const uint4*)(g_q2bf + ic * 2048))[tid];
            *(uint4*)(Bsb + (tid >> 2) * 80 + (tid & 3) * 16) = v;
        }
        // A build: copy pre-split bf16s (no converts), 16 taps/thread
        {
            const unsigned short* ph = ishh + abase0 + ic * 144;
            const unsigned short* pl = ishl + abase0 + ic * 144;
            unsigned hw[8], lw[8];
            if (ahalf == 0) {
                #pragma unroll
                for (int j = 0; j < 8; j++) {
                    const int t0 = 2 * j, t1 = t0 + 1;
                    const int o0 = (t0 / 5) * 12 + t0 % 5;
                    const int o1 = (t1 / 5) * 12 + t1 % 5;
                    hw[j] = (unsigned)ph[o0] | ((unsigned)ph[o1] << 16);
                    lw[j] = (unsigned)pl[o0] | ((unsigned)pl[o1] << 16);
                }
            } else {
                #pragma unroll
                for (int j = 0; j < 8; j++) {
                    const int t0 = 16 + 2 * j, t1 = t0 + 1;
                    unsigned h0 = 0, h1 = 0, l0 = 0, l1 = 0;
                    if (t0 < 25) { const int o0 = (t0 / 5) * 12 + t0 % 5; h0 = ph[o0]; l0 = pl[o0]; }
                    if (t1 < 25) { const int o1 = (t1 / 5) * 12 + t1 % 5; h1 = ph[o1]; l1 = pl[o1]; }
                    hw[j] = h0 | (h1 << 16);
                    lw[j] = l0 | (l1 << 16);
                }
            }
            unsigned char* da = Ahb + arow * 80 + ahalf * 32;
            *(uint4*)da        = make_uint4(hw[0], hw[1], hw[2], hw[3]);
            *(uint4*)(da + 16) = make_uint4(hw[4], hw[5], hw[6], hw[7]);
            unsigned char* dl = Alb + arow * 80 + ahalf * 32;
            *(uint4*)dl        = make_uint4(lw[0], lw[1], lw[2], lw[3]);
            *(uint4*)(dl + 16) = make_uint4(lw[4], lw[5], lw[6], lw[7]);
        }
        __syncthreads();
        // MMA: 2 k-steps x {hi,lo} x 2 m-tiles x 4 n-tiles
        #pragma unroll
        for (int ks = 0; ks < 2; ks++) {
            int kb = (ks * 16 + tig * 2) * 2;           // byte offset in row
            unsigned b0[4], b1[4];
            #pragma unroll
            for (int nt = 0; nt < 4; nt++) {
                const unsigned char* bp = Bsb + (n_w + nt * 8 + g) * 80 + kb;
                b0[nt] = *(const unsigned*)bp;
                b1[nt] = *(const unsigned*)(bp + 16);
            }
            #pragma unroll
            for (int var = 0; var < 2; var++) {
                const unsigned char* Ab = var ? Alb : Ahb;
                #pragma unroll
                for (int mt = 0; mt < 2; mt++) {
                    const unsigned char* ap = Ab + (m_w + mt * 16 + g) * 80 + kb;
                    unsigned a0 = *(const unsigned*)ap;
                    unsigned a1 = *(const unsigned*)(ap + 8 * 80);
                    unsigned a2 = *(const unsigned*)(ap + 16);
                    unsigned a3 = *(const unsigned*)(ap + 8 * 80 + 16);
                    #pragma unroll
                    for (int nt = 0; nt < 4; nt++)
                        mma_bf16(acc[mt][nt], a0, a1, a2, a3, b0[nt], b1[nt]);
                }
            }
        }
    }
    __syncthreads();                            // builds done; safe to reuse ish as Ds

    // write D fragments to Ds[128][65]
    #pragma unroll
    for (int mt = 0; mt < 2; mt++)
        #pragma unroll
        for (int nt = 0; nt < 4; nt++) {
            int r0 = m_w + mt * 16 + g, c0 = n_w + nt * 8 + tig * 2;
            Ds[r0 * 65 + c0]           = acc[mt][nt][0];
            Ds[r0 * 65 + c0 + 1]       = acc[mt][nt][1];
            Ds[(r0 + 8) * 65 + c0]     = acc[mt][nt][2];
            Ds[(r0 + 8) * 65 + c0 + 1] = acc[mt][nt][3];
        }
    __syncthreads();

    // bias + stats + maxpool: threads 0..127 = (img, oc)
    if (tid < 128) {
        int oc = tid & 63, im = tid >> 6;
        float bias = b2[oc];
        float ls = 0.f, lq = 0.f;
        #pragma unroll
        for (int py = 0; py < 4; py++)
            #pragma unroll
            for (int px = 0; px < 4; px++) {
                int r = im * 64 + py * 16 + px * 2;
                float v0 = Ds[r * 65 + oc] + bias;
                float v1 = Ds[(r + 1) * 65 + oc] + bias;
                float v2 = Ds[(r + 8) * 65 + oc] + bias;
                float v3 = Ds[(r + 9) * 65 + oc] + bias;
                ls += v0 + v1 + v2 + v3;
                lq = fmaf(v0, v0, lq); lq = fmaf(v1, v1, lq);
                lq = fmaf(v2, v2, lq); lq = fmaf(v3, v3, lq);
                float mx = fmaxf(fmaxf(v0, v1), fmaxf(v2, v3));
                g_pool2[((size_t)(n0 + im) * 64 + oc) * 16 + py * 4 + px] = mx;
            }
        atomicAdd(&ssum[oc], ls);
        atomicAdd(&ssq[oc], lq);
    }
    __syncthreads();
    if (tid < 64) { atomicAdd(&g_sum2[tid], ssum[tid]); atomicAdd(&g_sq2[tid], ssq[tid]); }
}

// ---------------- fc1 on mma.sync: C[4096,512] = relu(bn2(A)) @ qf1^T -------
// grid (32,4), 256 thr. CTA tile M=128, N=128, K chunks of 32 (oc pairs).
// Warp tile 32x64: m_w=(w>>1)*32, n_w=(w&1)*64; acc[2][8][4].
__global__ __launch_bounds__(256) void fc1_mma_kernel(const float* __restrict__ bf1) {
    __shared__ __align__(16) __nv_bfloat16 Ah[128 * 40];
    __shared__ __align__(16) __nv_bfloat16 Al[128 * 40];
    __shared__ __align__(16) __nv_bfloat16 Bs[128 * 40];
    __shared__ float bias_s[128], cs[128], cq[128];
    int tid = threadIdx.x, lane = tid & 31, w = tid >> 5;
    int g = lane >> 2, tig = lane & 3;
    int m0 = blockIdx.x * 128, j0 = blockIdx.y * 128;
    if (tid < 128) { bias_s[tid] = bf1[j0 + tid]; cs[tid] = 0.f; cq[tid] = 0.f; }

    int m_w = (w >> 1) * 32, n_w = (w & 1) * 64;
    float acc[2][8][4];
    #pragma unroll
    for (int mt = 0; mt < 2; mt++)
        #pragma unroll
        for (int nt = 0; nt < 8; nt++)
            #pragma unroll
            for (int q = 0; q < 4; q++) acc[mt][nt][q] = 0.f;

    int row = tid >> 1, half = tid & 1;

    for (int kc = 0; kc < 32; kc++) {
        __syncthreads();                   // prev MMA LDS done (WAR on A/B smem)
        // A fill: 16 k-values = one oc block; bn+relu + hi/lo split
        {
            int oc = kc * 2 + half;
            float sc = g_a2[oc], sd = g_d2[oc];
            const float4* ap4 = (const float4*)(g_pool2 + (size_t)(m0 + row) * 1024 + oc * 16);
            unsigned hw[8], lw[8];
            #pragma unroll
            for (int i = 0; i < 4; i++) {
                float4 r = ap4[i];
                float v0 = fmaxf(fmaf(sc, r.x, sd), 0.f);
                float v1 = fmaxf(fmaf(sc, r.y, sd), 0.f);
                float v2 = fmaxf(fmaf(sc, r.z, sd), 0.f);
                float v3 = fmaxf(fmaf(sc, r.w, sd), 0.f);
                __nv_bfloat162 h01 = __floats2bfloat162_rn(v0, v1);
                __nv_bfloat162 h23 = __floats2bfloat162_rn(v2, v3);
                float2 f01 = __bfloat1622float2(h01);
                float2 f23 = __bfloat1622float2(h23);
                __nv_bfloat162 l01 = __floats2bfloat162_rn(v0 - f01.x, v1 - f01.y);
                __nv_bfloat162 l23 = __floats2bfloat162_rn(v2 - f23.x, v3 - f23.y);
                memcpy(&hw[2 * i], &h01, 4); memcpy(&hw[2 * i + 1], &h23, 4);
                memcpy(&lw[2 * i], &l01, 4); memcpy(&lw[2 * i + 1], &l23, 4);
            }
            unsigned char* da = (unsigned char*)Ah + row * 80 + half * 32;
            *(uint4*)da        = make_uint4(hw[0], hw[1], hw[2], hw[3]);
            *(uint4*)(da + 16) = make_uint4(hw[4], hw[5], hw[6], hw[7]);
            unsigned char* dl = (unsigned char*)Al + row * 80 + half * 32;
            *(uint4*)dl        = make_uint4(lw[0], lw[1], lw[2], lw[3]);
            *(uint4*)(dl + 16) = make_uint4(lw[4], lw[5], lw[6], lw[7]);
        }
        // B fill: prebaked bf16, flat 32B per thread
        {
            const uint4* bp4 = (const uint4*)(g_qf1b + (size_t)(j0 + row) * 1024 + kc * 32 + half * 16);
            uint4 v0 = bp4[0], v1 = bp4[1];
            unsigned char* d = (unsigned char*)Bs + row * 80 + half * 32;
            *(uint4*)d        = v0;
            *(uint4*)(d + 16) = v1;
        }
        __syncthreads();
        // MMA
        #pragma unroll
        for (int ks = 0; ks < 2; ks++) {
            int kb = (ks * 16 + tig * 2) * 2;
            unsigned b0[8], b1[8];
            #pragma unroll
            for (int nt = 0; nt < 8; nt++) {
                const unsigned char* bp = (const unsigned char*)Bs + (n_w + nt * 8 + g) * 80 + kb;
                b0[nt] = *(const unsigned*)bp;
                b1[nt] = *(const unsigned*)(bp + 16);
            }
            #pragma unroll
            for (int var = 0; var < 2; var++) {
                const unsigned char* Ab = (const unsigned char*)(var ? Al : Ah);
                #pragma unroll
                for (int mt = 0; mt < 2; mt++) {
                    const unsigned char* ap = Ab + (m_w + mt * 16 + g) * 80 + kb;
                    unsigned a0 = *(const unsigned*)ap;
                    unsigned a1 = *(const unsigned*)(ap + 8 * 80);
                    unsigned a2 = *(const unsigned*)(ap + 16);
                    unsigned a3 = *(const unsigned*)(ap + 8 * 80 + 16);
                    #pragma unroll
                    for (int nt = 0; nt < 8; nt++)
                        mma_bf16(acc[mt][nt], a0, a1, a2, a3, b0[nt], b1[nt]);
                }
            }
        }
    }

    // epilogue: bias, write z, per-column stats
    #pragma unroll
    for (int mt = 0; mt < 2; mt++) {
        int r0 = m_w + mt * 16 + g;
        size_t gr0 = (size_t)(m0 + r0) * 512 + j0;
        size_t gr1 = (size_t)(m0 + r0 + 8) * 512 + j0;
        #pragma unroll
        for (int nt = 0; nt < 8; nt++) {
            int c0 = n_w + nt * 8 + tig * 2;
            float b0v = bias_s[c0], b1v = bias_s[c0 + 1];
            float v00 = acc[mt][nt][0] + b0v, v01 = acc[mt][nt][1] + b1v;
            float v10 = acc[mt][nt][2] + b0v, v11 = acc[mt][nt][3] + b1v;
            *(float2*)(g_z + gr0 + c0) = make_float2(v00, v01);
            *(float2*)(g_z + gr1 + c0) = make_float2(v10, v11);
            atomicAdd(&cs[c0],     v00 + v10);
            atomicAdd(&cs[c0 + 1], v01 + v11);
            atomicAdd(&cq[c0],     fmaf(v00, v00, v10 * v10));
            atomicAdd(&cq[c0 + 1], fmaf(v01, v01, v11 * v11));
        }
    }
    __syncthreads();
    if (tid < 128) { atomicAdd(&g_sum3[j0 + tid], cs[tid]); atomicAdd(&g_sq3[j0 + tid], cq[tid]); }
}

// ---------------- fc2: [4096,512] x [512,10], one warp per row ----------------
__global__ __launch_bounds__(256) void fc2_kernel(const float* __restrict__ bf2,
                                                  float* __restrict__ out) {
    int w = threadIdx.x >> 5, l = threadIdx.x & 31;
    int row = blockIdx.x * 8 + w;
    const float* zr = g_z + (size_t)row * 512;
    float acc[10];
    #pragma unroll
    for (int k = 0; k < 10; k++) acc[k] = 0.f;
    for (int j = l; j < 512; j += 32) {
        float h = fmaxf(fmaf(g_a3[j], zr[j], g_d3[j]), 0.f);
        #pragma unroll
        for (int k = 0; k < 10; k++) acc[k] = fmaf(h, g_qf2[k * 512 + j], acc[k]);
    }
    #pragma unroll
    for (int k = 0; k < 10; k++)
        #pragma unroll
        for (int o = 16; o; o >>= 1) acc[k] += __shfl_xor_sync(0xffffffffu, acc[k], o);
    if (l < 10) out[row * 10 + l] = acc[l] + bf2[l];
}

// ---------------- host entry ----------------
extern "C" void kernel_launch(void* const* d_in, const int* in_sizes, int n_in,
                              void* d_out, int out_size) {
    const float* x   = (const float*)d_in[0];
    const float* w1  = (const float*)d_in[1];
    const float* b1  = (const float*)d_in[2];
    const float* g1  = (const float*)d_in[3];
    const float* be1 = (const float*)d_in[4];
    const float* w2  = (const float*)d_in[5];
    const float* b2  = (const float*)d_in[6];
    const float* g2  = (const float*)d_in[7];
    const float* be2 = (const float*)d_in[8];
    const float* wf1 = (const float*)d_in[9];
    const float* bf1 = (const float*)d_in[10];
    const float* g3  = (const float*)d_in[11];
    const float* be3 = (const float*)d_in[12];
    const float* wf2 = (const float*)d_in[13];
    const float* bf2 = (const float*)d_in[14];
    float* out = (float*)d_out;

    cudaFuncSetAttribute(conv2_mma_kernel,
                         cudaFuncAttributeMaxDynamicSharedMemorySize, C2_DSM);

    zero_stats_kernel<<<1, 512>>>();

    maxabs_kernel<<<1,   256>>>(w1,  800,    0);
    maxabs_kernel<<<32,  256>>>(w2,  51200,  1);
    maxabs_kernel<<<256, 256>>>(wf1, 524288, 2);
    maxabs_kernel<<<4,   256>>>(wf2, 5120,   3);

    quantize_kernel<<<4,    256>>>(w1,  800,    0);
    quantize_w2_kernel<<<256, 256>>>(w2);
    quantize_kernel<<<2048, 256>>>(wf1, 524288, 2);
    quantize_kernel<<<20,   256>>>(wf2, 5120,   3);

    conv1_kernel<<<NIMG, 256>>>(x, b1);
    finalize_kernel<<<1, 32>>>(g1, be1, 0);

    conv2_mma_kernel<<<NIMG / 2, 256, C2_DSM>>>(b2);
    finalize_kernel<<<1, 64>>>(g2, be2, 1);

    fc1_mma_kernel<<<dim3(32, 4), 256>>>(bf1);
    finalize_kernel<<<2, 256>>>(g3, be3, 2);

    fc2_kernel<<<512, 256>>>(bf2, out);
}